// round 7
// baseline (speedup 1.0000x reference)
#include <cuda_runtime.h>
#include <cuda_bf16.h>
#include <cstdint>

// ---------------------------------------------------------------------------
// Fused Gaussian rasterizer, R7:
//  - 16x16 px tiles, 256 CTAs x 512 threads
//  - projection: 1 gaussian/thread (512 = NG)
//  - composite: 2 threads/pixel, depth-split halves combined via
//    (rgbF + TF*rgbB) monoid merge; batch-4 pipelined EX2 in each half
//  - opacity folded into exp2 bias; rank-scatter depth sort
// ---------------------------------------------------------------------------

#define NG    512
#define IMG   256
#define TW    16
#define TH    16
#define NT    512
#define NWARP (NT/32)

__device__ __forceinline__ float ex2(float x) {
    float y;
    asm("ex2.approx.ftz.f32 %0, %1;" : "=f"(y) : "f"(x));
    return y;
}

__global__ __launch_bounds__(NT, 2)
void gs_fused(const float* __restrict__ pos,
              const float* __restrict__ cov3d,
              const float* __restrict__ opac,
              const float* __restrict__ cols,
              const float* __restrict__ Km,
              const float* __restrict__ Rm,
              const float* __restrict__ tv,
              float* __restrict__ out)
{
    __shared__ float4             rec[NG][3];    // 24 KB depth-ordered records
    __shared__ unsigned long long skey[NG];      // 4 KB (reused as exchange)
    __shared__ int                warpTotals[NWARP];

    float4* xch = (float4*)skey;                 // 256 x float4 = 4 KB

    const int tid  = threadIdx.x;
    const int lane = tid & 31;
    const int wid  = tid >> 5;

    const int tileX = blockIdx.x * TW;
    const int tileY = blockIdx.y * TH;
    const float tX0 = (float)tileX, tX1 = (float)(tileX + TW);
    const float tY0 = (float)tileY, tY1 = (float)(tileY + TH);

    const float r00 = Rm[0], r01 = Rm[1], r02 = Rm[2];
    const float r10 = Rm[3], r11 = Rm[4], r12 = Rm[5];
    const float r20 = Rm[6], r21 = Rm[7], r22 = Rm[8];
    const float fx  = Km[0], fy = Km[4];

    // ---------------- phase 1: project gaussian g = tid ----------------
    const int g = tid;
    const float p0 = pos[3*g+0], p1 = pos[3*g+1], p2 = pos[3*g+2];

    const float cam0 = r00*p0 + r01*p1 + r02*p2 + tv[0];
    const float cam1 = r10*p0 + r11*p1 + r12*p2 + tv[1];
    const float cam2 = r20*p0 + r21*p1 + r22*p2 + tv[2];

    const float pr0 = Km[0]*cam0 + Km[1]*cam1 + Km[2]*cam2;
    const float pr1 = Km[3]*cam0 + Km[4]*cam1 + Km[5]*cam2;
    const float pr2 = Km[6]*cam0 + Km[7]*cam1 + Km[8]*cam2;
    const float rz = 1.0f / pr2;
    const float mx = pr0 * rz;
    const float my = pr1 * rz;

    const float z   = cam2;
    const float iz  = 1.0f / z;
    const float jx0 = fx * iz;
    const float jx2 = -fx * cam0 * iz * iz;
    const float jy1 = fy * iz;
    const float jy2 = -fy * cam1 * iz * iz;

    // P = J * R  (2x3)
    const float P00 = jx0*r00 + jx2*r20;
    const float P01 = jx0*r01 + jx2*r21;
    const float P02 = jx0*r02 + jx2*r22;
    const float P10 = jy1*r10 + jy2*r20;
    const float P11 = jy1*r11 + jy2*r21;
    const float P12 = jy1*r12 + jy2*r22;

    // symmetric C
    const float c00 = cov3d[9*g+0];
    const float c01 = cov3d[9*g+1];
    const float c02 = cov3d[9*g+2];
    const float c11 = cov3d[9*g+4];
    const float c12 = cov3d[9*g+5];
    const float c22 = cov3d[9*g+8];

    const float t00 = c00*P00 + c01*P01 + c02*P02;
    const float t01 = c01*P00 + c11*P01 + c12*P02;
    const float t02 = c02*P00 + c12*P01 + c22*P02;
    const float t10 = c00*P10 + c01*P11 + c02*P12;
    const float t11 = c01*P10 + c11*P11 + c12*P12;
    const float t12 = c02*P10 + c12*P11 + c22*P12;

    const float a = P00*t00 + P01*t01 + P02*t02 + 0.3f;
    const float b = P10*t00 + P11*t01 + P12*t02;
    const float c = P10*t10 + P11*t11 + P12*t12 + 0.3f;

    const float det  = fmaxf(a*c - b*b, 1e-8f);
    const float idet = 1.0f / det;
    // exp2 prescale: exp(-0.5*m) = exp2(-0.72134752*m)
    const float e00 = -0.72134752f * c * idet;
    const float e01 =  1.44269504f * b * idet;
    const float e11 = -0.72134752f * a * idet;

    const float hd = (a - c) * 0.5f;
    const float max_eig = (a + c)*0.5f + sqrtf(fmaxf(hd*hd + b*b, 1e-8f));
    const float radius = 3.0f * sqrtf(max_eig);

    const float x_min = fmaxf(0.0f,       truncf(mx - radius));
    const float x_max = fminf((float)IMG, truncf(mx + radius) + 1.0f);
    const float y_min = fmaxf(0.0f,       truncf(my - radius));
    const float y_max = fminf((float)IMG, truncf(my + radius) + 1.0f);

    // ---------------- phase 2: cull + compaction slot ----------------
    const bool flag = (x_min < tX1) && (x_max > tX0) &&
                      (y_min < tY1) && (y_max > tY0);

    const unsigned m = __ballot_sync(0xffffffffu, flag);
    if (lane == 0) warpTotals[wid] = __popc(m);
    __syncthreads();

    int offset = 0, count = 0;
    #pragma unroll
    for (int w = 0; w < NWARP; w++) {
        const int t = warpTotals[w];
        if (w < wid) offset += t;
        count += t;
    }
    const int pos_ = offset + __popc(m & ((1u << lane) - 1u));

    const unsigned long long mykey =
        ((unsigned long long)__float_as_uint(z) << 16) | (unsigned long long)g;
    if (flag) skey[pos_] = mykey;
    __syncthreads();

    // ---------------- phase 3: rank + scatter ----------------
    int rank = 0;
    if (flag) {
        for (int j = 0; j < count; j++)
            rank += (skey[j] < mykey);
    }
    __syncthreads();   // skey fully read before rec/xch aliasing later
    if (flag) {
        const float bias = __log2f(opac[g]);
        const unsigned lo = (unsigned)x_min | ((unsigned)x_max << 16);
        const unsigned hi = (unsigned)y_min | ((unsigned)y_max << 16);
        rec[rank][0] = make_float4(mx, my, e00, e01);
        rec[rank][1] = make_float4(e11, bias, cols[3*g+0], cols[3*g+1]);
        rec[rank][2] = make_float4(cols[3*g+2], __uint_as_float(lo),
                                   __uint_as_float(hi), 0.f);
    }
    const int countPad = (count + 3) & ~3;
    for (int t2 = count + tid; t2 < countPad; t2 += NT) {
        rec[t2][0] = make_float4(0.f, 0.f, 0.f, 0.f);
        rec[t2][1] = make_float4(0.f, 0.f, 0.f, 0.f);
        rec[t2][2] = make_float4(0.f, __uint_as_float(0xFFFFu),
                                 __uint_as_float(0xFFFFu), 0.f);
    }
    __syncthreads();

    // ---------------- phase 4: depth-split composite ----------------
    const int pix  = tid & 255;              // 0..255
    const int half = tid >> 8;               // 0 front, 1 back
    const int pxi = tileX + (pix & (TW - 1));
    const int pyi = tileY + (pix >> 4);
    const float pxf = (float)pxi;
    const float pyf = (float)pyi;

    const int mid = ((count + 7) >> 3) << 2;        // ~count/2, multiple of 4
    const int lo_ = half ? mid : 0;
    const int hi_ = half ? countPad : mid;

    float T = 1.0f, rr = 0.0f, gg = 0.0f, bb = 0.0f;
    for (int base = lo_; base < hi_; base += 4) {
        float4 q0[4], q1[4], q2[4];
        #pragma unroll
        for (int i = 0; i < 4; i++) {
            q0[i] = rec[base+i][0];
            q1[i] = rec[base+i][1];
            q2[i] = rec[base+i][2];
        }
        float gs[4];
        #pragma unroll
        for (int i = 0; i < 4; i++) {
            const unsigned lo = __float_as_uint(q2[i].y);
            const unsigned hi = __float_as_uint(q2[i].z);
            const int x0 = (int)(lo & 0xffffu), x1 = (int)(lo >> 16);
            const int y0 = (int)(hi & 0xffffu), y1 = (int)(hi >> 16);
            const bool inb = (pxi >= x0) & (pxi < x1) & (pyi >= y0) & (pyi < y1);
            const float dx = pxf - q0[i].x;
            const float dy = pyf - q0[i].y;
            const float u  = fmaf(q1[i].x * dy, dy, q1[i].y);   // e11*dy^2 + bias
            const float pl = fmaf(q0[i].w, dy, q0[i].z * dx);   // e01*dy + e00*dx
            const float e  = fmaf(pl, dx, u);
            gs[i] = inb ? ex2(e) : 0.0f;                        // alpha
        }
        #pragma unroll
        for (int i = 0; i < 4; i++) {
            const float tg = T * gs[i];
            rr = fmaf(tg, q1[i].z, rr);
            gg = fmaf(tg, q1[i].w, gg);
            bb = fmaf(tg, q2[i].x, bb);
            T  = T - tg;
        }
        if (T < 1e-5f) break;
    }

    // back half publishes partials; front half combines
    if (half) xch[pix] = make_float4(rr, gg, bb, 0.f);
    __syncthreads();
    if (!half) {
        const float4 bk = xch[pix];
        const int idx = (pyi * IMG + pxi) * 3;
        out[idx + 0] = fmaf(T, bk.x, rr);
        out[idx + 1] = fmaf(T, bk.y, gg);
        out[idx + 2] = fmaf(T, bk.z, bb);
    }
}

extern "C" void kernel_launch(void* const* d_in, const int* in_sizes, int n_in,
                              void* d_out, int out_size)
{
    const float* pos   = (const float*)d_in[0];  // (512,3)
    const float* cov3d = (const float*)d_in[1];  // (512,3,3)
    const float* opac  = (const float*)d_in[2];  // (512,1)
    const float* cols  = (const float*)d_in[3];  // (512,3)
    const float* Km    = (const float*)d_in[4];  // (3,3)
    const float* Rm    = (const float*)d_in[5];  // (3,3)
    const float* tv    = (const float*)d_in[6];  // (3,)
    float* out = (float*)d_out;                  // (256,256,3)

    gs_fused<<<dim3(IMG/TW, IMG/TH), NT>>>(pos, cov3d, opac, cols, Km, Rm, tv, out);
}